// round 10
// baseline (speedup 1.0000x reference)
#include <cuda_runtime.h>
#include <cstdint>

#define FIN 128
#define HH  128
#define C3  384
#define MAXN 50000
#define MAXE 800000
#define BM 128
#define BN 128
#define BKT 32
#define BSP 136   // Bs row stride (conflict-free: bank = 8*(k%4)+gid)

// ---------------- static device scratch ----------------
__device__ float d_scr[(size_t)MAXN * C3];    // [aggG | aggC | xr]
__device__ float d_h[(size_t)MAXN * C3];
__device__ float d_meanb[(size_t)MAXN * HH];
__device__ float d_z1[(size_t)MAXN * 256];
__device__ float d_z2[(size_t)MAXN * 128];
__device__ float d_as[MAXN], d_ad[MAXN], d_dinv[MAXN];
__device__ int   d_deg[MAXN];
__device__ int   d_rowptr[MAXN + 1];
__device__ int   d_cursor[MAXN];
__device__ int   d_srclist[MAXE];
__device__ int   d_bsum[256], d_boff[256];
__device__ float d_was[FIN], d_wad[FIN];
__device__ float d_sum[C3], d_sumsq[C3], d_bns[C3], d_bnt[C3];
__device__ int   d_is32;

#define TAG_EXT   (-1)
#define TAG_AGGG  0
#define TAG_AGGC  1
#define TAG_XR    2
#define TAG_H     3
#define TAG_H128  4
#define TAG_H256  5
#define TAG_MEANB 6
#define TAG_Z1    7
#define TAG_Z2    8
#define TAG_BNS   9
#define TAG_BNT   10

__device__ __forceinline__ const float* resolve_c(int tag, const float* ext) {
    switch (tag) {
        case TAG_AGGG:  return d_scr;
        case TAG_AGGC:  return d_scr + (size_t)MAXN * 128;
        case TAG_XR:    return d_scr + (size_t)2 * MAXN * 128;
        case TAG_H:     return d_h;
        case TAG_H128:  return d_h + 128;
        case TAG_H256:  return d_h + 256;
        case TAG_MEANB: return d_meanb;
        case TAG_Z1:    return d_z1;
        case TAG_Z2:    return d_z2;
        case TAG_BNS:   return d_bns;
        case TAG_BNT:   return d_bnt;
        default:        return ext;
    }
}
__device__ __forceinline__ float* resolve_m(int tag, float* ext) {
    switch (tag) {
        case TAG_AGGG:  return d_scr;
        case TAG_AGGC:  return d_scr + (size_t)MAXN * 128;
        case TAG_XR:    return d_scr + (size_t)2 * MAXN * 128;
        case TAG_H:     return d_h;
        case TAG_H128:  return d_h + 128;
        case TAG_H256:  return d_h + 256;
        case TAG_MEANB: return d_meanb;
        case TAG_Z1:    return d_z1;
        case TAG_Z2:    return d_z2;
        default:        return ext;
    }
}

__device__ __forceinline__ int edge_get(const void* ei, size_t i, int n) {
    long long v = d_is32 ? (long long)((const int*)ei)[i]
                         : ((const long long*)ei)[i];
    if (v < 0) v = 0;
    if (v >= n) v = n - 1;
    return (int)v;
}

// ---------------- fused prep: detect + init + watt ----------------
__global__ void prep_kernel(const void* ei, int E, int n,
                            const float* __restrict__ Wg,
                            const float* __restrict__ att_s,
                            const float* __restrict__ att_d) {
    int tid = threadIdx.x, bid = blockIdx.x;
    int gi = bid * 256 + tid;
    int warp = tid >> 5, lane = tid & 31;

    if (bid == 0 && warp == 0) {
        int bad = 0;
        if (lane < 16) {
            size_t idx = ((size_t)lane * 2654435761u) % (size_t)E;
            long long v = ((const long long*)ei)[idx];
            if (v < 0 || v >= (long long)n) bad = 1;
        }
        unsigned m = __ballot_sync(0xffffffffu, bad);
        if (lane == 0) d_is32 = (m ? 1 : 0);
    }
    if (gi < n) d_deg[gi] = 0;
    if (gi < C3) { d_sum[gi] = 0.f; d_sumsq[gi] = 0.f; }
    int k = bid * 8 + warp;
    if (bid < 16 && k < FIN) {
        float4 w4 = ((const float4*)(Wg + (size_t)k * FIN))[lane];
        float4 a4 = ((const float4*)att_s)[lane];
        float4 b4 = ((const float4*)att_d)[lane];
        float s1 = w4.x * a4.x + w4.y * a4.y + w4.z * a4.z + w4.w * a4.w;
        float s2 = w4.x * b4.x + w4.y * b4.y + w4.z * b4.z + w4.w * b4.w;
        #pragma unroll
        for (int off = 16; off > 0; off >>= 1) {
            s1 += __shfl_down_sync(0xffffffffu, s1, off);
            s2 += __shfl_down_sync(0xffffffffu, s2, off);
        }
        if (lane == 0) { d_was[k] = s1; d_wad[k] = s2; }
    }
}

// ---------------- edge pipeline ----------------
__global__ void asad_kernel(const float* __restrict__ x, int n) {
    int w = (blockIdx.x * blockDim.x + threadIdx.x) >> 5;
    int lane = threadIdx.x & 31;
    if (w >= n) return;
    float4 h4 = ((const float4*)(x + (size_t)w * FIN))[lane];
    float4 s4 = ((const float4*)d_was)[lane];
    float4 t4 = ((const float4*)d_wad)[lane];
    float ss = h4.x * s4.x + h4.y * s4.y + h4.z * s4.z + h4.w * s4.w;
    float sd = h4.x * t4.x + h4.y * t4.y + h4.z * t4.z + h4.w * t4.w;
    #pragma unroll
    for (int off = 16; off > 0; off >>= 1) {
        ss += __shfl_down_sync(0xffffffffu, ss, off);
        sd += __shfl_down_sync(0xffffffffu, sd, off);
    }
    if (lane == 0) { d_as[w] = ss; d_ad[w] = sd; }
}

__global__ void count_deg_kernel(const void* __restrict__ ei, int E, int n) {
    int e = blockIdx.x * blockDim.x + threadIdx.x;
    if (e < E) atomicAdd(&d_deg[edge_get(ei, (size_t)E + e, n)], 1);
}

// ---------------- 3-phase parallel scan ----------------
__global__ void scan1_kernel(int n) {
    __shared__ int sh[256];
    int tid = threadIdx.x;
    int i = blockIdx.x * 256 + tid;
    int v = (i < n) ? d_deg[i] : 0;
    sh[tid] = v;
    __syncthreads();
    #pragma unroll
    for (int off = 128; off > 0; off >>= 1) {
        if (tid < off) sh[tid] += sh[tid + off];
        __syncthreads();
    }
    if (tid == 0) d_bsum[blockIdx.x] = sh[0];
}

__global__ void scan2_kernel(int nb, int n) {
    __shared__ int sh[256];
    int tid = threadIdx.x;
    int v = (tid < nb) ? d_bsum[tid] : 0;
    sh[tid] = v;
    __syncthreads();
    #pragma unroll
    for (int off = 1; off < 256; off <<= 1) {
        int add = (tid >= off) ? sh[tid - off] : 0;
        __syncthreads();
        sh[tid] += add;
        __syncthreads();
    }
    if (tid < nb) d_boff[tid] = sh[tid] - v;
    if (tid == 255) d_rowptr[n] = sh[255];
}

__global__ void scan3_kernel(int n) {
    __shared__ int sh[256];
    int tid = threadIdx.x;
    int i = blockIdx.x * 256 + tid;
    int v = (i < n) ? d_deg[i] : 0;
    sh[tid] = v;
    __syncthreads();
    #pragma unroll
    for (int off = 1; off < 256; off <<= 1) {
        int add = (tid >= off) ? sh[tid - off] : 0;
        __syncthreads();
        sh[tid] += add;
        __syncthreads();
    }
    if (i < n) {
        int excl = d_boff[blockIdx.x] + sh[tid] - v;
        d_rowptr[i] = excl;
        d_cursor[i] = excl;
        d_dinv[i] = rsqrtf((float)v + 1.0f);
    }
}

__global__ void scatter_kernel(const void* __restrict__ ei, int E, int n) {
    int e = blockIdx.x * blockDim.x + threadIdx.x;
    if (e < E) {
        int s = edge_get(ei, (size_t)e, n);
        int d = edge_get(ei, (size_t)E + e, n);
        int pos = atomicAdd(&d_cursor[d], 1);
        if (pos >= 0 && pos < MAXE) d_srclist[pos] = s;
    }
}

__device__ __forceinline__ float lrelu02(float e) { return e > 0.f ? e : 0.2f * e; }

__global__ void gather_kernel(const float* __restrict__ x, int n) {
    int node = (blockIdx.x * blockDim.x + threadIdx.x) >> 5;
    int lane = threadIdx.x & 31;
    if (node >= n) return;
    int beg = d_rowptr[node], end = d_rowptr[node + 1];
    float adi = d_ad[node];
    float dvi = d_dinv[node];

    float4 gat, gcn;
    float4 sg = make_float4(0, 0, 0, 0);
    float den;

    {
        float w = __expf(lrelu02(d_as[node] + adi));
        den = w;
        float nn = dvi * dvi;
        float4 xv = ((const float4*)(x + (size_t)node * FIN))[lane];
        gat = make_float4(w * xv.x, w * xv.y, w * xv.z, w * xv.w);
        gcn = make_float4(nn * xv.x, nn * xv.y, nn * xv.z, nn * xv.w);
    }

    for (int j0 = beg; j0 < end; j0 += 32) {
        int myj = j0 + lane;
        int s = 0; float w = 0.f, nrm = 0.f;
        if (myj < end) {
            s = d_srclist[myj];
            w = __expf(lrelu02(d_as[s] + adi));
            nrm = d_dinv[s] * dvi;
        }
        int cnt = min(32, end - j0);
        for (int q = 0; q < cnt; q++) {
            int   ss = __shfl_sync(0xffffffffu, s, q);
            float wq = __shfl_sync(0xffffffffu, w, q);
            float nq = __shfl_sync(0xffffffffu, nrm, q);
            float4 xv = ((const float4*)(x + (size_t)ss * FIN))[lane];
            gat.x += wq * xv.x; gat.y += wq * xv.y; gat.z += wq * xv.z; gat.w += wq * xv.w;
            gcn.x += nq * xv.x; gcn.y += nq * xv.y; gcn.z += nq * xv.z; gcn.w += nq * xv.w;
            sg.x += xv.x; sg.y += xv.y; sg.z += xv.z; sg.w += xv.w;
            den += wq;
        }
    }

    float invden = 1.0f / den;
    float invcnt = 1.0f / fmaxf((float)(end - beg), 1.0f);
    float4 og = make_float4(gat.x * invden, gat.y * invden,
                            gat.z * invden, gat.w * invden);
    float4 om = make_float4(sg.x * invcnt, sg.y * invcnt,
                            sg.z * invcnt, sg.w * invcnt);
    ((float4*)(d_scr + (size_t)node * 128))[lane] = og;
    ((float4*)(d_scr + (size_t)MAXN * 128 + (size_t)node * 128))[lane] = gcn;
    ((float4*)(d_meanb + (size_t)node * HH))[lane] = om;
}

__global__ void bn_stats_kernel(int n) {
    int c = threadIdx.x;
    float s = 0.f, s2 = 0.f;
    for (int r = blockIdx.x; r < n; r += gridDim.x) {
        float v = d_h[(size_t)r * C3 + c];
        s += v; s2 += v * v;
    }
    atomicAdd(&d_sum[c], s);
    atomicAdd(&d_sumsq[c], s2);
}

__global__ void bn_final_kernel(const float* __restrict__ gamma,
                                const float* __restrict__ beta, int n) {
    int c = threadIdx.x;
    if (c < C3) {
        float invn = 1.0f / (float)n;
        float mu = d_sum[c] * invn;
        float var = d_sumsq[c] * invn - mu * mu;
        float r = rsqrtf(var + 1e-5f);
        d_bns[c] = r * gamma[c];
        d_bnt[c] = beta[c] - mu * r * gamma[c];
    }
}

// ---------------- TF32 GEMM: 4 warps, 64x64 warp tile ----------------
__device__ __forceinline__ uint32_t f2tf32(float f) {
    uint32_t o; asm("cvt.rna.tf32.f32 %0, %1;" : "=r"(o) : "f"(f)); return o;
}
__device__ __forceinline__ void mma_tf32(float* c, const uint32_t* a, const uint32_t* b) {
    asm volatile(
        "mma.sync.aligned.m16n8k8.row.col.f32.tf32.tf32.f32 "
        "{%0,%1,%2,%3}, {%4,%5,%6,%7}, {%8,%9}, {%0,%1,%2,%3};"
        : "+f"(c[0]), "+f"(c[1]), "+f"(c[2]), "+f"(c[3])
        : "r"(a[0]), "r"(a[1]), "r"(a[2]), "r"(a[3]), "r"(b[0]), "r"(b[1]));
}

__global__ void __launch_bounds__(128)
gemm_tc_kernel(int aTag, const float* aExt, int lda,
               int bTag, const float* bExt, int ldb,
               int cTag, float* cExt, int ldc,
               int M, int K, int Ncol,
               const float* __restrict__ bias,
               int addTag, int ldadd,
               int scaleTag, int shiftTag, int reluA) {
    const float* __restrict__ A = resolve_c(aTag, aExt);
    const float* __restrict__ B = resolve_c(bTag, bExt);
    float* __restrict__ C = resolve_m(cTag, cExt);
    const float* __restrict__ addv   = (addTag   == TAG_EXT) ? nullptr : resolve_c(addTag, nullptr);
    const float* __restrict__ ascale = (scaleTag == TAG_EXT) ? nullptr : resolve_c(scaleTag, nullptr);
    const float* __restrict__ ashift = (shiftTag == TAG_EXT) ? nullptr : resolve_c(shiftTag, nullptr);

    __shared__ float As[BM][BKT + 4];
    __shared__ float Bs[BKT][BSP];

    int tid  = threadIdx.x;              // 0..127
    int warp = tid >> 5, lane = tid & 31;
    int wm = warp & 1, wn = warp >> 1;   // 2x2 warps, 64x64 tiles
    int gid = lane >> 2, tig = lane & 3;
    int row0 = blockIdx.y * BM, col0 = blockIdx.x * BN;

    float acc[4][8][4];
    #pragma unroll
    for (int mt = 0; mt < 4; mt++)
        #pragma unroll
        for (int nt = 0; nt < 8; nt++)
            #pragma unroll
            for (int r = 0; r < 4; r++) acc[mt][nt][r] = 0.f;

    int gm = row0 + tid;   // A: thread owns one row per tile
    for (int k0 = 0; k0 < K; k0 += BKT) {
        #pragma unroll
        for (int i = 0; i < 8; i++) {
            float4 v = make_float4(0.f, 0.f, 0.f, 0.f);
            if (gm < M) v = *(const float4*)(A + (size_t)gm * lda + k0 + i * 4);
            if (ascale) {
                int gk = k0 + i * 4;
                v.x = v.x * ascale[gk + 0] + ashift[gk + 0];
                v.y = v.y * ascale[gk + 1] + ashift[gk + 1];
                v.z = v.z * ascale[gk + 2] + ashift[gk + 2];
                v.w = v.w * ascale[gk + 3] + ashift[gk + 3];
            }
            if (reluA) {
                v.x = fmaxf(v.x, 0.f); v.y = fmaxf(v.y, 0.f);
                v.z = fmaxf(v.z, 0.f); v.w = fmaxf(v.w, 0.f);
            }
            As[tid][i * 4 + 0] = __uint_as_float(f2tf32(v.x));
            As[tid][i * 4 + 1] = __uint_as_float(f2tf32(v.y));
            As[tid][i * 4 + 2] = __uint_as_float(f2tf32(v.z));
            As[tid][i * 4 + 3] = __uint_as_float(f2tf32(v.w));
        }
        #pragma unroll
        for (int i = 0; i < 8; i++) {
            int k = warp + 4 * i;        // 0..31
            int nc = lane * 4;
            float4 v = make_float4(0.f, 0.f, 0.f, 0.f);
            if (col0 + nc < Ncol)
                v = *(const float4*)(B + (size_t)(k0 + k) * ldb + col0 + nc);
            Bs[k][nc + 0] = __uint_as_float(f2tf32(v.x));
            Bs[k][nc + 1] = __uint_as_float(f2tf32(v.y));
            Bs[k][nc + 2] = __uint_as_float(f2tf32(v.z));
            Bs[k][nc + 3] = __uint_as_float(f2tf32(v.w));
        }
        __syncthreads();

        #pragma unroll
        for (int ks = 0; ks < BKT; ks += 8) {
            uint32_t af[4][4];
            #pragma unroll
            for (int mt = 0; mt < 4; mt++) {
                int m = wm * 64 + mt * 16;
                af[mt][0] = __float_as_uint(As[m + gid    ][ks + tig    ]);
                af[mt][1] = __float_as_uint(As[m + gid + 8][ks + tig    ]);
                af[mt][2] = __float_as_uint(As[m + gid    ][ks + tig + 4]);
                af[mt][3] = __float_as_uint(As[m + gid + 8][ks + tig + 4]);
            }
            uint32_t bf[8][2];
            #pragma unroll
            for (int nt = 0; nt < 8; nt++) {
                int nn = wn * 64 + nt * 8 + gid;
                bf[nt][0] = __float_as_uint(Bs[ks + tig    ][nn]);
                bf[nt][1] = __float_as_uint(Bs[ks + tig + 4][nn]);
            }
            #pragma unroll
            for (int mt = 0; mt < 4; mt++)
                #pragma unroll
                for (int nt = 0; nt < 8; nt++)
                    mma_tf32(acc[mt][nt], af[mt], bf[nt]);
        }
        __syncthreads();
    }

    #pragma unroll
    for (int mt = 0; mt < 4; mt++) {
        #pragma unroll
        for (int nt = 0; nt < 8; nt++) {
            int n0 = col0 + wn * 64 + nt * 8 + 2 * tig;
            if (n0 >= Ncol) continue;
            float b0 = bias ? bias[n0] : 0.f;
            float b1 = bias ? bias[n0 + 1] : 0.f;
            #pragma unroll
            for (int half = 0; half < 2; half++) {
                int r = row0 + wm * 64 + mt * 16 + gid + half * 8;
                if (r >= M) continue;
                float v0 = acc[mt][nt][half * 2 + 0] + b0;
                float v1 = acc[mt][nt][half * 2 + 1] + b1;
                if (addv) {
                    v0 += addv[(size_t)r * ldadd + n0];
                    v1 += addv[(size_t)r * ldadd + n0 + 1];
                }
                *(float2*)(C + (size_t)r * ldc + n0) = make_float2(v0, v1);
            }
        }
    }
}

// grouped convs: p0 aggG@Wg+bg; p1 aggC@Wc+bc; p2 x@Wr -> xr
__global__ void __launch_bounds__(128)
conv3_kernel(int rbn, int M, const float* __restrict__ x,
             const float* __restrict__ Wg, const float* __restrict__ Wc,
             const float* __restrict__ Wr,
             const float* __restrict__ b_gat, const float* __restrict__ b_gcn) {
    int p = blockIdx.x / rbn;
    int rb = blockIdx.x % rbn;
    const float *A, *B, *bias; float* C; int ldc;
    if (p == 0)      { A = d_scr;                      B = Wg; C = d_h;       bias = b_gat; ldc = C3; }
    else if (p == 1) { A = d_scr + (size_t)MAXN * 128; B = Wc; C = d_h + 128; bias = b_gcn; ldc = C3; }
    else             { A = x;                          B = Wr; C = d_scr + (size_t)2 * MAXN * 128; bias = nullptr; ldc = 128; }
    const int K = 128, lda = 128, ldb = 128;

    __shared__ float As[BM][BKT + 4];
    __shared__ float Bs[BKT][BSP];

    int tid  = threadIdx.x;
    int warp = tid >> 5, lane = tid & 31;
    int wm = warp & 1, wn = warp >> 1;
    int gid = lane >> 2, tig = lane & 3;
    int row0 = rb * BM;

    float acc[4][8][4];
    #pragma unroll
    for (int mt = 0; mt < 4; mt++)
        #pragma unroll
        for (int nt = 0; nt < 8; nt++)
            #pragma unroll
            for (int r = 0; r < 4; r++) acc[mt][nt][r] = 0.f;

    int gm = row0 + tid;
    for (int k0 = 0; k0 < K; k0 += BKT) {
        #pragma unroll
        for (int i = 0; i < 8; i++) {
            float4 v = make_float4(0.f, 0.f, 0.f, 0.f);
            if (gm < M) v = *(const float4*)(A + (size_t)gm * lda + k0 + i * 4);
            As[tid][i * 4 + 0] = __uint_as_float(f2tf32(v.x));
            As[tid][i * 4 + 1] = __uint_as_float(f2tf32(v.y));
            As[tid][i * 4 + 2] = __uint_as_float(f2tf32(v.z));
            As[tid][i * 4 + 3] = __uint_as_float(f2tf32(v.w));
        }
        #pragma unroll
        for (int i = 0; i < 8; i++) {
            int k = warp + 4 * i;
            int nc = lane * 4;
            float4 v = *(const float4*)(B + (size_t)(k0 + k) * ldb + nc);
            Bs[k][nc + 0] = __uint_as_float(f2tf32(v.x));
            Bs[k][nc + 1] = __uint_as_float(f2tf32(v.y));
            Bs[k][nc + 2] = __uint_as_float(f2tf32(v.z));
            Bs[k][nc + 3] = __uint_as_float(f2tf32(v.w));
        }
        __syncthreads();

        #pragma unroll
        for (int ks = 0; ks < BKT; ks += 8) {
            uint32_t af[4][4];
            #pragma unroll
            for (int mt = 0; mt < 4; mt++) {
                int m = wm * 64 + mt * 16;
                af[mt][0] = __float_as_uint(As[m + gid    ][ks + tig    ]);
                af[mt][1] = __float_as_uint(As[m + gid + 8][ks + tig    ]);
                af[mt][2] = __float_as_uint(As[m + gid    ][ks + tig + 4]);
                af[mt][3] = __float_as_uint(As[m + gid + 8][ks + tig + 4]);
            }
            uint32_t bf[8][2];
            #pragma unroll
            for (int nt = 0; nt < 8; nt++) {
                int nn = wn * 64 + nt * 8 + gid;
                bf[nt][0] = __float_as_uint(Bs[ks + tig    ][nn]);
                bf[nt][1] = __float_as_uint(Bs[ks + tig + 4][nn]);
            }
            #pragma unroll
            for (int mt = 0; mt < 4; mt++)
                #pragma unroll
                for (int nt = 0; nt < 8; nt++)
                    mma_tf32(acc[mt][nt], af[mt], bf[nt]);
        }
        __syncthreads();
    }

    #pragma unroll
    for (int mt = 0; mt < 4; mt++) {
        #pragma unroll
        for (int nt = 0; nt < 8; nt++) {
            int n0 = wn * 64 + nt * 8 + 2 * tig;
            float b0 = bias ? bias[n0] : 0.f;
            float b1 = bias ? bias[n0 + 1] : 0.f;
            #pragma unroll
            for (int half = 0; half < 2; half++) {
                int r = row0 + wm * 64 + mt * 16 + gid + half * 8;
                if (r >= M) continue;
                float v0 = acc[mt][nt][half * 2 + 0] + b0;
                float v1 = acc[mt][nt][half * 2 + 1] + b1;
                *(float2*)(C + (size_t)r * ldc + n0) = make_float2(v0, v1);
            }
        }
    }
}

static void launch_gemm(int aTag, const float* aExt, int lda,
                        int bTag, const float* bExt, int ldb,
                        int cTag, float* cExt, int ldc,
                        int M, int K, int Ncol,
                        const float* bias,
                        int addTag, int ldadd,
                        int scaleTag, int shiftTag, int reluA) {
    dim3 g((Ncol + BN - 1) / BN, (M + BM - 1) / BM);
    gemm_tc_kernel<<<g, 128>>>(aTag, aExt, lda, bTag, bExt, ldb, cTag, cExt, ldc,
                               M, K, Ncol, bias, addTag, ldadd,
                               scaleTag, shiftTag, reluA);
}

// ---------------- launch ----------------
extern "C" void kernel_launch(void* const* d_in, const int* in_sizes, int n_in,
                              void* d_out, int out_size) {
    const float* x        = (const float*)d_in[0];
    const void*  ei       = d_in[1];
    const float* W_gat    = (const float*)d_in[2];
    const float* att_src  = (const float*)d_in[3];
    const float* att_dst  = (const float*)d_in[4];
    const float* b_gat    = (const float*)d_in[5];
    const float* W_gcn    = (const float*)d_in[6];
    const float* b_gcn    = (const float*)d_in[7];
    const float* W_sage_l = (const float*)d_in[8];
    const float* b_sage_l = (const float*)d_in[9];
    const float* W_sage_r = (const float*)d_in[10];
    const float* W1       = (const float*)d_in[11];
    const float* b1       = (const float*)d_in[12];
    const float* W2       = (const float*)d_in[13];
    const float* b2       = (const float*)d_in[14];
    const float* W3       = (const float*)d_in[15];
    const float* b3       = (const float*)d_in[16];
    const float* gamma    = (const float*)d_in[17];
    const float* beta     = (const float*)d_in[18];
    float* out = (float*)d_out;

    int N = in_sizes[0] / FIN;
    int E = in_sizes[1] / 2;
    int rbn = (N + BM - 1) / BM;
    int sbn = (N + 255) / 256;

    prep_kernel<<<(N + 255) / 256, 256>>>(ei, E, N, W_gat, att_src, att_dst);
    asad_kernel<<<(N * 32 + 255) / 256, 256>>>(x, N);
    count_deg_kernel<<<(E + 255) / 256, 256>>>(ei, E, N);
    scan1_kernel<<<sbn, 256>>>(N);
    scan2_kernel<<<1, 256>>>(sbn, N);
    scan3_kernel<<<sbn, 256>>>(N);
    scatter_kernel<<<(E + 255) / 256, 256>>>(ei, E, N);
    gather_kernel<<<(N * 32 + 255) / 256, 256>>>(x, N);
    conv3_kernel<<<3 * rbn, 128>>>(rbn, N, x, W_gat, W_gcn, W_sage_r, b_gat, b_gcn);
    launch_gemm(TAG_MEANB, nullptr, HH, TAG_EXT, W_sage_l, HH, TAG_H256, nullptr, C3,
                N, HH, HH, b_sage_l, TAG_XR, 128, TAG_EXT, TAG_EXT, 0);
    bn_stats_kernel<<<1024, C3>>>(N);
    bn_final_kernel<<<1, C3>>>(gamma, beta, N);
    launch_gemm(TAG_H, nullptr, C3, TAG_EXT, W1, 256, TAG_Z1, nullptr, 256,
                N, C3, 256, b1, TAG_EXT, 0, TAG_BNS, TAG_BNT, 1);
    launch_gemm(TAG_Z1, nullptr, 256, TAG_EXT, W2, 128, TAG_Z2, nullptr, 128,
                N, 256, 128, b2, TAG_EXT, 0, TAG_EXT, TAG_EXT, 1);
    launch_gemm(TAG_Z2, nullptr, 128, TAG_EXT, W3, 40, TAG_EXT, out, 40,
                N, 128, 40, b3, TAG_EXT, 0, TAG_EXT, TAG_EXT, 1);
}

// round 13
// speedup vs baseline: 1.2623x; 1.2623x over previous
#include <cuda_runtime.h>
#include <cstdint>

#define FIN 128
#define HH  128
#define C3  384
#define MAXN 50000
#define MAXE 800000
#define BM 128
#define BN 128
#define BKT 32

// ---------------- static device scratch ----------------
__device__ float d_scr[(size_t)MAXN * C3];    // [aggG | aggC | xr]
__device__ float d_h[(size_t)MAXN * C3];
__device__ float d_meanb[(size_t)MAXN * HH];
__device__ float d_z1[(size_t)MAXN * 256];
__device__ float d_z2[(size_t)MAXN * 128];
__device__ float d_as[MAXN], d_ad[MAXN], d_dinv[MAXN];
__device__ int   d_deg[MAXN];
__device__ int   d_rowptr[MAXN + 1];
__device__ int   d_cursor[MAXN];
__device__ int   d_srclist[MAXE];
__device__ int   d_bsum[256], d_boff[256];
__device__ float d_was[FIN], d_wad[FIN];
__device__ float d_sum[C3], d_sumsq[C3], d_bns[C3], d_bnt[C3];
__device__ int   d_is32;

#define TAG_EXT   (-1)
#define TAG_AGGG  0
#define TAG_AGGC  1
#define TAG_XR    2
#define TAG_H     3
#define TAG_H128  4
#define TAG_H256  5
#define TAG_MEANB 6
#define TAG_Z1    7
#define TAG_Z2    8
#define TAG_BNS   9
#define TAG_BNT   10

__device__ __forceinline__ const float* resolve_c(int tag, const float* ext) {
    switch (tag) {
        case TAG_AGGG:  return d_scr;
        case TAG_AGGC:  return d_scr + (size_t)MAXN * 128;
        case TAG_XR:    return d_scr + (size_t)2 * MAXN * 128;
        case TAG_H:     return d_h;
        case TAG_H128:  return d_h + 128;
        case TAG_H256:  return d_h + 256;
        case TAG_MEANB: return d_meanb;
        case TAG_Z1:    return d_z1;
        case TAG_Z2:    return d_z2;
        case TAG_BNS:   return d_bns;
        case TAG_BNT:   return d_bnt;
        default:        return ext;
    }
}
__device__ __forceinline__ float* resolve_m(int tag, float* ext) {
    switch (tag) {
        case TAG_AGGG:  return d_scr;
        case TAG_AGGC:  return d_scr + (size_t)MAXN * 128;
        case TAG_XR:    return d_scr + (size_t)2 * MAXN * 128;
        case TAG_H:     return d_h;
        case TAG_H128:  return d_h + 128;
        case TAG_H256:  return d_h + 256;
        case TAG_MEANB: return d_meanb;
        case TAG_Z1:    return d_z1;
        case TAG_Z2:    return d_z2;
        default:        return ext;
    }
}

__device__ __forceinline__ int edge_get(const void* ei, size_t i, int n) {
    long long v = d_is32 ? (long long)((const int*)ei)[i]
                         : ((const long long*)ei)[i];
    if (v < 0) v = 0;
    if (v >= n) v = n - 1;
    return (int)v;
}

// ---------------- fused prep: detect + init + watt ----------------
__global__ void prep_kernel(const void* ei, int E, int n,
                            const float* __restrict__ Wg,
                            const float* __restrict__ att_s,
                            const float* __restrict__ att_d) {
    int tid = threadIdx.x, bid = blockIdx.x;
    int gi = bid * 256 + tid;
    int warp = tid >> 5, lane = tid & 31;

    if (bid == 0 && warp == 0) {
        int bad = 0;
        if (lane < 16) {
            size_t idx = ((size_t)lane * 2654435761u) % (size_t)E;
            long long v = ((const long long*)ei)[idx];
            if (v < 0 || v >= (long long)n) bad = 1;
        }
        unsigned m = __ballot_sync(0xffffffffu, bad);
        if (lane == 0) d_is32 = (m ? 1 : 0);
    }
    if (gi < n) d_deg[gi] = 0;
    if (gi < C3) { d_sum[gi] = 0.f; d_sumsq[gi] = 0.f; }
    int k = bid * 8 + warp;
    if (bid < 16 && k < FIN) {
        float4 w4 = ((const float4*)(Wg + (size_t)k * FIN))[lane];
        float4 a4 = ((const float4*)att_s)[lane];
        float4 b4 = ((const float4*)att_d)[lane];
        float s1 = w4.x * a4.x + w4.y * a4.y + w4.z * a4.z + w4.w * a4.w;
        float s2 = w4.x * b4.x + w4.y * b4.y + w4.z * b4.z + w4.w * b4.w;
        #pragma unroll
        for (int off = 16; off > 0; off >>= 1) {
            s1 += __shfl_down_sync(0xffffffffu, s1, off);
            s2 += __shfl_down_sync(0xffffffffu, s2, off);
        }
        if (lane == 0) { d_was[k] = s1; d_wad[k] = s2; }
    }
}

// ---------------- edge pipeline ----------------
__global__ void asad_kernel(const float* __restrict__ x, int n) {
    int w = (blockIdx.x * blockDim.x + threadIdx.x) >> 5;
    int lane = threadIdx.x & 31;
    if (w >= n) return;
    float4 h4 = ((const float4*)(x + (size_t)w * FIN))[lane];
    float4 s4 = ((const float4*)d_was)[lane];
    float4 t4 = ((const float4*)d_wad)[lane];
    float ss = h4.x * s4.x + h4.y * s4.y + h4.z * s4.z + h4.w * s4.w;
    float sd = h4.x * t4.x + h4.y * t4.y + h4.z * t4.z + h4.w * t4.w;
    #pragma unroll
    for (int off = 16; off > 0; off >>= 1) {
        ss += __shfl_down_sync(0xffffffffu, ss, off);
        sd += __shfl_down_sync(0xffffffffu, sd, off);
    }
    if (lane == 0) { d_as[w] = ss; d_ad[w] = sd; }
}

__global__ void count_deg_kernel(const void* __restrict__ ei, int E, int n) {
    int e = blockIdx.x * blockDim.x + threadIdx.x;
    if (e < E) atomicAdd(&d_deg[edge_get(ei, (size_t)E + e, n)], 1);
}

// ---------------- 3-phase parallel scan ----------------
__global__ void scan1_kernel(int n) {
    __shared__ int sh[256];
    int tid = threadIdx.x;
    int i = blockIdx.x * 256 + tid;
    int v = (i < n) ? d_deg[i] : 0;
    sh[tid] = v;
    __syncthreads();
    #pragma unroll
    for (int off = 128; off > 0; off >>= 1) {
        if (tid < off) sh[tid] += sh[tid + off];
        __syncthreads();
    }
    if (tid == 0) d_bsum[blockIdx.x] = sh[0];
}

__global__ void scan2_kernel(int nb, int n) {
    __shared__ int sh[256];
    int tid = threadIdx.x;
    int v = (tid < nb) ? d_bsum[tid] : 0;
    sh[tid] = v;
    __syncthreads();
    #pragma unroll
    for (int off = 1; off < 256; off <<= 1) {
        int add = (tid >= off) ? sh[tid - off] : 0;
        __syncthreads();
        sh[tid] += add;
        __syncthreads();
    }
    if (tid < nb) d_boff[tid] = sh[tid] - v;
    if (tid == 255) d_rowptr[n] = sh[255];
}

__global__ void scan3_kernel(int n) {
    __shared__ int sh[256];
    int tid = threadIdx.x;
    int i = blockIdx.x * 256 + tid;
    int v = (i < n) ? d_deg[i] : 0;
    sh[tid] = v;
    __syncthreads();
    #pragma unroll
    for (int off = 1; off < 256; off <<= 1) {
        int add = (tid >= off) ? sh[tid - off] : 0;
        __syncthreads();
        sh[tid] += add;
        __syncthreads();
    }
    if (i < n) {
        int excl = d_boff[blockIdx.x] + sh[tid] - v;
        d_rowptr[i] = excl;
        d_cursor[i] = excl;
        d_dinv[i] = rsqrtf((float)v + 1.0f);
    }
}

__global__ void scatter_kernel(const void* __restrict__ ei, int E, int n) {
    int e = blockIdx.x * blockDim.x + threadIdx.x;
    if (e < E) {
        int s = edge_get(ei, (size_t)e, n);
        int d = edge_get(ei, (size_t)E + e, n);
        int pos = atomicAdd(&d_cursor[d], 1);
        if (pos >= 0 && pos < MAXE) d_srclist[pos] = s;
    }
}

__device__ __forceinline__ float lrelu02(float e) { return e > 0.f ? e : 0.2f * e; }

__global__ void gather_kernel(const float* __restrict__ x, int n) {
    int node = (blockIdx.x * blockDim.x + threadIdx.x) >> 5;
    int lane = threadIdx.x & 31;
    if (node >= n) return;
    int beg = d_rowptr[node], end = d_rowptr[node + 1];
    float adi = d_ad[node];
    float dvi = d_dinv[node];

    float4 gat, gcn;
    float4 sg = make_float4(0, 0, 0, 0);
    float den;

    {
        float w = __expf(lrelu02(d_as[node] + adi));
        den = w;
        float nn = dvi * dvi;
        float4 xv = ((const float4*)(x + (size_t)node * FIN))[lane];
        gat = make_float4(w * xv.x, w * xv.y, w * xv.z, w * xv.w);
        gcn = make_float4(nn * xv.x, nn * xv.y, nn * xv.z, nn * xv.w);
    }

    for (int j0 = beg; j0 < end; j0 += 32) {
        int myj = j0 + lane;
        int s = 0; float w = 0.f, nrm = 0.f;
        if (myj < end) {
            s = d_srclist[myj];
            w = __expf(lrelu02(d_as[s] + adi));
            nrm = d_dinv[s] * dvi;
        }
        int cnt = min(32, end - j0);
        for (int q = 0; q < cnt; q++) {
            int   ss = __shfl_sync(0xffffffffu, s, q);
            float wq = __shfl_sync(0xffffffffu, w, q);
            float nq = __shfl_sync(0xffffffffu, nrm, q);
            float4 xv = ((const float4*)(x + (size_t)ss * FIN))[lane];
            gat.x += wq * xv.x; gat.y += wq * xv.y; gat.z += wq * xv.z; gat.w += wq * xv.w;
            gcn.x += nq * xv.x; gcn.y += nq * xv.y; gcn.z += nq * xv.z; gcn.w += nq * xv.w;
            sg.x += xv.x; sg.y += xv.y; sg.z += xv.z; sg.w += xv.w;
            den += wq;
        }
    }

    float invden = 1.0f / den;
    float invcnt = 1.0f / fmaxf((float)(end - beg), 1.0f);
    float4 og = make_float4(gat.x * invden, gat.y * invden,
                            gat.z * invden, gat.w * invden);
    float4 om = make_float4(sg.x * invcnt, sg.y * invcnt,
                            sg.z * invcnt, sg.w * invcnt);
    ((float4*)(d_scr + (size_t)node * 128))[lane] = og;
    ((float4*)(d_scr + (size_t)MAXN * 128 + (size_t)node * 128))[lane] = gcn;
    ((float4*)(d_meanb + (size_t)node * HH))[lane] = om;
}

__global__ void bn_final_kernel(const float* __restrict__ gamma,
                                const float* __restrict__ beta, int n) {
    int c = threadIdx.x;
    if (c < C3) {
        float invn = 1.0f / (float)n;
        float mu = d_sum[c] * invn;
        float var = d_sumsq[c] * invn - mu * mu;
        float r = rsqrtf(var + 1e-5f);
        d_bns[c] = r * gamma[c];
        d_bnt[c] = beta[c] - mu * r * gamma[c];
    }
}

// ---------------- TF32 tensor-core GEMM (R9-proven mainloop, 256 thr, 32x64 warp tiles) ----------------
__device__ __forceinline__ uint32_t f2tf32(float f) {
    uint32_t o; asm("cvt.rna.tf32.f32 %0, %1;" : "=r"(o) : "f"(f)); return o;
}
__device__ __forceinline__ void mma_tf32(float* c, const uint32_t* a, const uint32_t* b) {
    asm volatile(
        "mma.sync.aligned.m16n8k8.row.col.f32.tf32.tf32.f32 "
        "{%0,%1,%2,%3}, {%4,%5,%6,%7}, {%8,%9}, {%0,%1,%2,%3};"
        : "+f"(c[0]), "+f"(c[1]), "+f"(c[2]), "+f"(c[3])
        : "r"(a[0]), "r"(a[1]), "r"(a[2]), "r"(a[3]), "r"(b[0]), "r"(b[1]));
}

// statsOff >= 0: accumulate column sums/sumsq of written values into
// d_sum/d_sumsq at [statsOff + local_col] (BN stats fusion).
__global__ void __launch_bounds__(256)
gemm_tc_kernel(int aTag, const float* aExt, int lda,
               int bTag, const float* bExt, int ldb,
               int cTag, float* cExt, int ldc,
               int M, int K, int Ncol,
               const float* __restrict__ bias,
               int addTag, int ldadd,
               int scaleTag, int shiftTag, int reluA, int statsOff) {
    const float* __restrict__ A = resolve_c(aTag, aExt);
    const float* __restrict__ B = resolve_c(bTag, bExt);
    float* __restrict__ C = resolve_m(cTag, cExt);
    const float* __restrict__ addv   = (addTag   == TAG_EXT) ? nullptr : resolve_c(addTag, nullptr);
    const float* __restrict__ ascale = (scaleTag == TAG_EXT) ? nullptr : resolve_c(scaleTag, nullptr);
    const float* __restrict__ ashift = (shiftTag == TAG_EXT) ? nullptr : resolve_c(shiftTag, nullptr);

    __shared__ float As[BM][BKT + 4];
    __shared__ float Bs[BKT][BN + 4];

    int tid  = threadIdx.x;
    int warp = tid >> 5, lane = tid & 31;
    int wm = warp & 3, wn = warp >> 2;
    int gid = lane >> 2, tig = lane & 3;
    int row0 = blockIdx.y * BM, col0 = blockIdx.x * BN;

    float acc[2][8][4];
    #pragma unroll
    for (int mt = 0; mt < 2; mt++)
        #pragma unroll
        for (int nt = 0; nt < 8; nt++)
            #pragma unroll
            for (int r = 0; r < 4; r++) acc[mt][nt][r] = 0.f;

    int a_m  = tid >> 3;
    int a_k4 = (tid & 7) * 4;

    for (int k0 = 0; k0 < K; k0 += BKT) {
        #pragma unroll
        for (int i = 0; i < 4; i++) {
            int m = a_m + 32 * i;
            int gm = row0 + m;
            float4 v = make_float4(0.f, 0.f, 0.f, 0.f);
            if (gm < M) v = *(const float4*)(A + (size_t)gm * lda + k0 + a_k4);
            if (ascale) {
                int gk = k0 + a_k4;
                v.x = v.x * ascale[gk + 0] + ashift[gk + 0];
                v.y = v.y * ascale[gk + 1] + ashift[gk + 1];
                v.z = v.z * ascale[gk + 2] + ashift[gk + 2];
                v.w = v.w * ascale[gk + 3] + ashift[gk + 3];
            }
            if (reluA) {
                v.x = fmaxf(v.x, 0.f); v.y = fmaxf(v.y, 0.f);
                v.z = fmaxf(v.z, 0.f); v.w = fmaxf(v.w, 0.f);
            }
            As[m][a_k4 + 0] = __uint_as_float(f2tf32(v.x));
            As[m][a_k4 + 1] = __uint_as_float(f2tf32(v.y));
            As[m][a_k4 + 2] = __uint_as_float(f2tf32(v.z));
            As[m][a_k4 + 3] = __uint_as_float(f2tf32(v.w));
        }
        #pragma unroll
        for (int i = 0; i < 4; i++) {
            int idx = tid + 256 * i;
            int k = idx >> 5;
            int nc = (idx & 31) * 4;
            float4 v = make_float4(0.f, 0.f, 0.f, 0.f);
            if (col0 + nc < Ncol)
                v = *(const float4*)(B + (size_t)(k0 + k) * ldb + col0 + nc);
            Bs[k][nc + 0] = __uint_as_float(f2tf32(v.x));
            Bs[k][nc + 1] = __uint_as_float(f2tf32(v.y));
            Bs[k][nc + 2] = __uint_as_float(f2tf32(v.z));
            Bs[k][nc + 3] = __uint_as_float(f2tf32(v.w));
        }
        __syncthreads();

        #pragma unroll
        for (int ks = 0; ks < BKT; ks += 8) {
            uint32_t af[2][4];
            #pragma unroll
            for (int mt = 0; mt < 2; mt++) {
                int m = wm * 32 + mt * 16;
                af[mt][0] = __float_as_uint(As[m + gid    ][ks + tig    ]);
                af[mt][1] = __float_as_uint(As[m + gid + 8][ks + tig    ]);
                af[mt][2] = __float_as_uint(As[m + gid    ][ks + tig + 4]);
                af[mt][3] = __float_as_uint(As[m + gid + 8][ks + tig + 4]);
            }
            uint32_t bf[8][2];
            #pragma unroll
            for (int nt = 0; nt < 8; nt++) {
                int nn = wn * 64 + nt * 8 + gid;
                bf[nt][0] = __float_as_uint(Bs[ks + tig    ][nn]);
                bf[nt][1] = __float_as_uint(Bs[ks + tig + 4][nn]);
            }
            #pragma unroll
            for (int mt = 0; mt < 2; mt++)
                #pragma unroll
                for (int nt = 0; nt < 8; nt++)
                    mma_tf32(acc[mt][nt], af[mt], bf[nt]);
        }
        __syncthreads();
    }

    #pragma unroll
    for (int nt = 0; nt < 8; nt++) {
        int n0 = col0 + wn * 64 + nt * 8 + 2 * tig;
        float sum0 = 0.f, sum1 = 0.f, sq0 = 0.f, sq1 = 0.f;
        if (n0 < Ncol) {
            float b0 = bias ? bias[n0] : 0.f;
            float b1 = bias ? bias[n0 + 1] : 0.f;
            #pragma unroll
            for (int mt = 0; mt < 2; mt++) {
                #pragma unroll
                for (int half = 0; half < 2; half++) {
                    int r = row0 + wm * 32 + mt * 16 + gid + half * 8;
                    if (r < M) {
                        float v0 = acc[mt][nt][half * 2 + 0] + b0;
                        float v1 = acc[mt][nt][half * 2 + 1] + b1;
                        if (addv) {
                            v0 += addv[(size_t)r * ldadd + n0];
                            v1 += addv[(size_t)r * ldadd + n0 + 1];
                        }
                        *(float2*)(C + (size_t)r * ldc + n0) = make_float2(v0, v1);
                        sum0 += v0; sq0 += v0 * v0;
                        sum1 += v1; sq1 += v1 * v1;
                    }
                }
            }
        }
        if (statsOff >= 0) {
            #pragma unroll
            for (int off = 16; off >= 4; off >>= 1) {
                sum0 += __shfl_down_sync(0xffffffffu, sum0, off);
                sq0  += __shfl_down_sync(0xffffffffu, sq0,  off);
                sum1 += __shfl_down_sync(0xffffffffu, sum1, off);
                sq1  += __shfl_down_sync(0xffffffffu, sq1,  off);
            }
            if (gid == 0 && n0 < Ncol) {
                int c = statsOff + n0 - col0;
                atomicAdd(&d_sum[c],     sum0);
                atomicAdd(&d_sumsq[c],   sq0);
                atomicAdd(&d_sum[c + 1], sum1);
                atomicAdd(&d_sumsq[c + 1], sq1);
            }
        }
    }
}

// grouped convs: p0 aggG@Wg+bg -> h[:,0:128] (+stats); p1 aggC@Wc+bc -> h[:,128:256] (+stats);
// p2 x@Wr -> xr (no stats)
__global__ void __launch_bounds__(256)
conv3_kernel(int rbn, int M, const float* __restrict__ x,
             const float* __restrict__ Wg, const float* __restrict__ Wc,
             const float* __restrict__ Wr,
             const float* __restrict__ b_gat, const float* __restrict__ b_gcn) {
    int p = blockIdx.x / rbn;
    int rb = blockIdx.x % rbn;
    const float *A, *B, *bias; float* C; int ldc, statsOff;
    if (p == 0)      { A = d_scr;                      B = Wg; C = d_h;       bias = b_gat; ldc = C3;  statsOff = 0; }
    else if (p == 1) { A = d_scr + (size_t)MAXN * 128; B = Wc; C = d_h + 128; bias = b_gcn; ldc = C3;  statsOff = 128; }
    else             { A = x;                          B = Wr; C = d_scr + (size_t)2 * MAXN * 128; bias = nullptr; ldc = 128; statsOff = -1; }
    const int K = 128, lda = 128, ldb = 128;

    __shared__ float As[BM][BKT + 4];
    __shared__ float Bs[BKT][BN + 4];

    int tid  = threadIdx.x;
    int warp = tid >> 5, lane = tid & 31;
    int wm = warp & 3, wn = warp >> 2;
    int gid = lane >> 2, tig = lane & 3;
    int row0 = rb * BM;

    float acc[2][8][4];
    #pragma unroll
    for (int mt = 0; mt < 2; mt++)
        #pragma unroll
        for (int nt = 0; nt < 8; nt++)
            #pragma unroll
            for (int r = 0; r < 4; r++) acc[mt][nt][r] = 0.f;

    int a_m  = tid >> 3;
    int a_k4 = (tid & 7) * 4;

    for (int k0 = 0; k0 < K; k0 += BKT) {
        #pragma unroll
        for (int i = 0; i < 4; i++) {
            int m = a_m + 32 * i;
            int gm = row0 + m;
            float4 v = make_float4(0.f, 0.f, 0.f, 0.f);
            if (gm < M) v = *(const float4*)(A + (size_t)gm * lda + k0 + a_k4);
            As[m][a_k4 + 0] = __uint_as_float(f2tf32(v.x));
            As[m][a_k4 + 1] = __uint_as_float(f2tf32(v.y));
            As[m][a_k4 + 2] = __uint_as_float(f2tf32(v.z));
            As[m][a_k4 + 3] = __uint_as_float(f2tf32(v.w));
        }
        #pragma unroll
        for (int i = 0; i < 4; i++) {
            int idx = tid + 256 * i;
            int k = idx >> 5;
            int nc = (idx & 31) * 4;
            float4 v = *(const float4*)(B + (size_t)(k0 + k) * ldb + nc);
            Bs[k][nc + 0] = __uint_as_float(f2tf32(v.x));
            Bs[k][nc + 1] = __uint_as_float(f2tf32(v.y));
            Bs[k][nc + 2] = __uint_as_float(f2tf32(v.z));
            Bs[k][nc + 3] = __uint_as_float(f2tf32(v.w));
        }
        __syncthreads();

        #pragma unroll
        for (int ks = 0; ks < BKT; ks += 8) {
            uint32_t af[2][4];
            #pragma unroll
            for (int mt = 0; mt < 2; mt++) {
                int m = wm * 32 + mt * 16;
                af[mt][0] = __float_as_uint(As[m + gid    ][ks + tig    ]);
                af[mt][1] = __float_as_uint(As[m + gid + 8][ks + tig    ]);
                af[mt][2] = __float_as_uint(As[m + gid    ][ks + tig + 4]);
                af[mt][3] = __float_as_uint(As[m + gid + 8][ks + tig + 4]);
            }
            uint32_t bf[8][2];
            #pragma unroll
            for (int nt = 0; nt < 8; nt++) {
                int nn = wn * 64 + nt * 8 + gid;
                bf[nt][0] = __float_as_uint(Bs[ks + tig    ][nn]);
                bf[nt][1] = __float_as_uint(Bs[ks + tig + 4][nn]);
            }
            #pragma unroll
            for (int mt = 0; mt < 2; mt++)
                #pragma unroll
                for (int nt = 0; nt < 8; nt++)
                    mma_tf32(acc[mt][nt], af[mt], bf[nt]);
        }
        __syncthreads();
    }

    #pragma unroll
    for (int nt = 0; nt < 8; nt++) {
        int n0 = wn * 64 + nt * 8 + 2 * tig;
        float b0 = bias ? bias[n0] : 0.f;
        float b1 = bias ? bias[n0 + 1] : 0.f;
        float sum0 = 0.f, sum1 = 0.f, sq0 = 0.f, sq1 = 0.f;
        #pragma unroll
        for (int mt = 0; mt < 2; mt++) {
            #pragma unroll
            for (int half = 0; half < 2; half++) {
                int r = row0 + wm * 32 + mt * 16 + gid + half * 8;
                if (r < M) {
                    float v0 = acc[mt][nt][half * 2 + 0] + b0;
                    float v1 = acc[mt][nt][half * 2 + 1] + b1;
                    *(float2*)(C + (size_t)r * ldc + n0) = make_float2(v0, v1);
                    sum0 += v0; sq0 += v0 * v0;
                    sum1 += v1; sq1 += v1 * v1;
                }
            }
        }
        if (statsOff >= 0) {
            #pragma unroll
            for (int off = 16; off >= 4; off >>= 1) {
                sum0 += __shfl_down_sync(0xffffffffu, sum0, off);
                sq0  += __shfl_down_sync(0xffffffffu, sq0,  off);
                sum1 += __shfl_down_sync(0xffffffffu, sum1, off);
                sq1  += __shfl_down_sync(0xffffffffu, sq1,  off);
            }
            if (gid == 0) {
                int c = statsOff + n0;
                atomicAdd(&d_sum[c],     sum0);
                atomicAdd(&d_sumsq[c],   sq0);
                atomicAdd(&d_sum[c + 1], sum1);
                atomicAdd(&d_sumsq[c + 1], sq1);
            }
        }
    }
}

static void launch_gemm(int aTag, const float* aExt, int lda,
                        int bTag, const float* bExt, int ldb,
                        int cTag, float* cExt, int ldc,
                        int M, int K, int Ncol,
                        const float* bias,
                        int addTag, int ldadd,
                        int scaleTag, int shiftTag, int reluA, int statsOff) {
    dim3 g((Ncol + BN - 1) / BN, (M + BM - 1) / BM);
    gemm_tc_kernel<<<g, 256>>>(aTag, aExt, lda, bTag, bExt, ldb, cTag, cExt, ldc,
                               M, K, Ncol, bias, addTag, ldadd,
                               scaleTag, shiftTag, reluA, statsOff);
}

// ---------------- launch ----------------
extern "C" void kernel_launch(void* const* d_in, const int* in_sizes, int n_in,
                              void* d_out, int out_size) {
    const float* x        = (const float*)d_in[0];
    const void*  ei       = d_in[1];
    const float* W_gat    = (const float*)d_in[2];
    const float* att_src  = (const float*)d_in[3];
    const float* att_dst  = (const float*)d_in[4];
    const float* b_gat    = (const float*)d_in[5];
    const float* W_gcn    = (const float*)d_in[6];
    const float* b_gcn    = (const float*)d_in[7];
    const float* W_sage_l = (const float*)d_in[8];
    const float* b_sage_l = (const float*)d_in[9];
    const float* W_sage_r = (const float*)d_in[10];
    const float* W1       = (const float*)d_in[11];
    const float* b1       = (const float*)d_in[12];
    const float* W2       = (const float*)d_in[13];
    const float* b2       = (const float*)d_in[14];
    const float* W3       = (const float*)d_in[15];
    const float* b3       = (const float*)d_in[16];
    const float* gamma    = (const float*)d_in[17];
    const float* beta     = (const float*)d_in[18];
    float* out = (float*)d_out;

    int N = in_sizes[0] / FIN;
    int E = in_sizes[1] / 2;
    int rbn = (N + BM - 1) / BM;
    int sbn = (N + 255) / 256;

    prep_kernel<<<(N + 255) / 256, 256>>>(ei, E, N, W_gat, att_src, att_dst);
    asad_kernel<<<(N * 32 + 255) / 256, 256>>>(x, N);
    count_deg_kernel<<<(E + 255) / 256, 256>>>(ei, E, N);
    scan1_kernel<<<sbn, 256>>>(N);
    scan2_kernel<<<1, 256>>>(sbn, N);
    scan3_kernel<<<sbn, 256>>>(N);
    scatter_kernel<<<(E + 255) / 256, 256>>>(ei, E, N);
    gather_kernel<<<(N * 32 + 255) / 256, 256>>>(x, N);
    // grouped convs (+BN stats for h[:,0:256])
    conv3_kernel<<<3 * rbn, 256>>>(rbn, N, x, W_gat, W_gcn, W_sage_r, b_gat, b_gcn);
    // sage: h[:,256:384] = meanb @ W_sage_l + b_sage_l + xr (+BN stats for cols 256:384)
    launch_gemm(TAG_MEANB, nullptr, HH, TAG_EXT, W_sage_l, HH, TAG_H256, nullptr, C3,
                N, HH, HH, b_sage_l, TAG_XR, 128, TAG_EXT, TAG_EXT, 0, 256);
    bn_final_kernel<<<1, C3>>>(gamma, beta, N);
    // MLP1
    launch_gemm(TAG_H, nullptr, C3, TAG_EXT, W1, 256, TAG_Z1, nullptr, 256,
                N, C3, 256, b1, TAG_EXT, 0, TAG_BNS, TAG_BNT, 1, -1);
    // MLP2
    launch_gemm(TAG_Z1, nullptr, 256, TAG_EXT, W2, 128, TAG_Z2, nullptr, 128,
                N, 256, 128, b2, TAG_EXT, 0, TAG_EXT, TAG_EXT, 1, -1);
    // MLP3
    launch_gemm(TAG_Z2, nullptr, 128, TAG_EXT, W3, 40, TAG_EXT, out, 40,
                N, 128, 40, b3, TAG_EXT, 0, TAG_EXT, TAG_EXT, 1, -1);
}

// round 15
// speedup vs baseline: 1.2984x; 1.0286x over previous
#include <cuda_runtime.h>
#include <cstdint>

#define FIN 128
#define HH  128
#define C3  384
#define MAXN 50000
#define MAXE 800000
#define BM 128
#define BN 128
#define BKT 32
#define ASP 36    // As row stride: conflict-free frag reads (4*gid+tig) + STS.128 writes
#define BSP 136   // Bs row stride: conflict-free frag reads (8*tig+gid) + STS.128 writes

// ---------------- static device scratch ----------------
__device__ float d_scr[(size_t)MAXN * C3];    // [aggG | aggC | xr]
__device__ float d_h[(size_t)MAXN * C3];
__device__ float d_meanb[(size_t)MAXN * HH];
__device__ float d_z1[(size_t)MAXN * 256];
__device__ float d_z2[(size_t)MAXN * 128];
__device__ float d_as[MAXN], d_ad[MAXN], d_dinv[MAXN];
__device__ int   d_deg[MAXN];
__device__ int   d_rowptr[MAXN + 1];
__device__ int   d_cursor[MAXN];
__device__ int   d_srclist[MAXE];
__device__ int   d_bsum[256], d_boff[256];
__device__ float d_was[FIN], d_wad[FIN];
__device__ float d_sum[C3], d_sumsq[C3], d_bns[C3], d_bnt[C3];
__device__ int   d_is32;

#define TAG_EXT   (-1)
#define TAG_AGGG  0
#define TAG_AGGC  1
#define TAG_XR    2
#define TAG_H     3
#define TAG_H128  4
#define TAG_H256  5
#define TAG_MEANB 6
#define TAG_Z1    7
#define TAG_Z2    8
#define TAG_BNS   9
#define TAG_BNT   10

__device__ __forceinline__ const float* resolve_c(int tag, const float* ext) {
    switch (tag) {
        case TAG_AGGG:  return d_scr;
        case TAG_AGGC:  return d_scr + (size_t)MAXN * 128;
        case TAG_XR:    return d_scr + (size_t)2 * MAXN * 128;
        case TAG_H:     return d_h;
        case TAG_H128:  return d_h + 128;
        case TAG_H256:  return d_h + 256;
        case TAG_MEANB: return d_meanb;
        case TAG_Z1:    return d_z1;
        case TAG_Z2:    return d_z2;
        case TAG_BNS:   return d_bns;
        case TAG_BNT:   return d_bnt;
        default:        return ext;
    }
}
__device__ __forceinline__ float* resolve_m(int tag, float* ext) {
    switch (tag) {
        case TAG_AGGG:  return d_scr;
        case TAG_AGGC:  return d_scr + (size_t)MAXN * 128;
        case TAG_XR:    return d_scr + (size_t)2 * MAXN * 128;
        case TAG_H:     return d_h;
        case TAG_H128:  return d_h + 128;
        case TAG_H256:  return d_h + 256;
        case TAG_MEANB: return d_meanb;
        case TAG_Z1:    return d_z1;
        case TAG_Z2:    return d_z2;
        default:        return ext;
    }
}

__device__ __forceinline__ int edge_get(const void* ei, size_t i, int n) {
    long long v = d_is32 ? (long long)((const int*)ei)[i]
                         : ((const long long*)ei)[i];
    if (v < 0) v = 0;
    if (v >= n) v = n - 1;
    return (int)v;
}

// ---------------- fused prep: detect + init + watt ----------------
__global__ void prep_kernel(const void* ei, int E, int n,
                            const float* __restrict__ Wg,
                            const float* __restrict__ att_s,
                            const float* __restrict__ att_d) {
    int tid = threadIdx.x, bid = blockIdx.x;
    int gi = bid * 256 + tid;
    int warp = tid >> 5, lane = tid & 31;

    if (bid == 0 && warp == 0) {
        int bad = 0;
        if (lane < 16) {
            size_t idx = ((size_t)lane * 2654435761u) % (size_t)E;
            long long v = ((const long long*)ei)[idx];
            if (v < 0 || v >= (long long)n) bad = 1;
        }
        unsigned m = __ballot_sync(0xffffffffu, bad);
        if (lane == 0) d_is32 = (m ? 1 : 0);
    }
    if (gi < n) d_deg[gi] = 0;
    if (gi < C3) { d_sum[gi] = 0.f; d_sumsq[gi] = 0.f; }
    int k = bid * 8 + warp;
    if (bid < 16 && k < FIN) {
        float4 w4 = ((const float4*)(Wg + (size_t)k * FIN))[lane];
        float4 a4 = ((const float4*)att_s)[lane];
        float4 b4 = ((const float4*)att_d)[lane];
        float s1 = w4.x * a4.x + w4.y * a4.y + w4.z * a4.z + w4.w * a4.w;
        float s2 = w4.x * b4.x + w4.y * b4.y + w4.z * b4.z + w4.w * b4.w;
        #pragma unroll
        for (int off = 16; off > 0; off >>= 1) {
            s1 += __shfl_down_sync(0xffffffffu, s1, off);
            s2 += __shfl_down_sync(0xffffffffu, s2, off);
        }
        if (lane == 0) { d_was[k] = s1; d_wad[k] = s2; }
    }
}

// ---------------- edge pipeline ----------------
__global__ void asad_kernel(const float* __restrict__ x, int n) {
    int w = (blockIdx.x * blockDim.x + threadIdx.x) >> 5;
    int lane = threadIdx.x & 31;
    if (w >= n) return;
    float4 h4 = ((const float4*)(x + (size_t)w * FIN))[lane];
    float4 s4 = ((const float4*)d_was)[lane];
    float4 t4 = ((const float4*)d_wad)[lane];
    float ss = h4.x * s4.x + h4.y * s4.y + h4.z * s4.z + h4.w * s4.w;
    float sd = h4.x * t4.x + h4.y * t4.y + h4.z * t4.z + h4.w * t4.w;
    #pragma unroll
    for (int off = 16; off > 0; off >>= 1) {
        ss += __shfl_down_sync(0xffffffffu, ss, off);
        sd += __shfl_down_sync(0xffffffffu, sd, off);
    }
    if (lane == 0) { d_as[w] = ss; d_ad[w] = sd; }
}

__global__ void count_deg_kernel(const void* __restrict__ ei, int E, int n) {
    int e = blockIdx.x * blockDim.x + threadIdx.x;
    if (e < E) atomicAdd(&d_deg[edge_get(ei, (size_t)E + e, n)], 1);
}

// ---------------- 3-phase parallel scan ----------------
__global__ void scan1_kernel(int n) {
    __shared__ int sh[256];
    int tid = threadIdx.x;
    int i = blockIdx.x * 256 + tid;
    int v = (i < n) ? d_deg[i] : 0;
    sh[tid] = v;
    __syncthreads();
    #pragma unroll
    for (int off = 128; off > 0; off >>= 1) {
        if (tid < off) sh[tid] += sh[tid + off];
        __syncthreads();
    }
    if (tid == 0) d_bsum[blockIdx.x] = sh[0];
}

__global__ void scan2_kernel(int nb, int n) {
    __shared__ int sh[256];
    int tid = threadIdx.x;
    int v = (tid < nb) ? d_bsum[tid] : 0;
    sh[tid] = v;
    __syncthreads();
    #pragma unroll
    for (int off = 1; off < 256; off <<= 1) {
        int add = (tid >= off) ? sh[tid - off] : 0;
        __syncthreads();
        sh[tid] += add;
        __syncthreads();
    }
    if (tid < nb) d_boff[tid] = sh[tid] - v;
    if (tid == 255) d_rowptr[n] = sh[255];
}

__global__ void scan3_kernel(int n) {
    __shared__ int sh[256];
    int tid = threadIdx.x;
    int i = blockIdx.x * 256 + tid;
    int v = (i < n) ? d_deg[i] : 0;
    sh[tid] = v;
    __syncthreads();
    #pragma unroll
    for (int off = 1; off < 256; off <<= 1) {
        int add = (tid >= off) ? sh[tid - off] : 0;
        __syncthreads();
        sh[tid] += add;
        __syncthreads();
    }
    if (i < n) {
        int excl = d_boff[blockIdx.x] + sh[tid] - v;
        d_rowptr[i] = excl;
        d_cursor[i] = excl;
        d_dinv[i] = rsqrtf((float)v + 1.0f);
    }
}

__global__ void scatter_kernel(const void* __restrict__ ei, int E, int n) {
    int e = blockIdx.x * blockDim.x + threadIdx.x;
    if (e < E) {
        int s = edge_get(ei, (size_t)e, n);
        int d = edge_get(ei, (size_t)E + e, n);
        int pos = atomicAdd(&d_cursor[d], 1);
        if (pos >= 0 && pos < MAXE) d_srclist[pos] = s;
    }
}

__device__ __forceinline__ float lrelu02(float e) { return e > 0.f ? e : 0.2f * e; }

__global__ void gather_kernel(const float* __restrict__ x, int n) {
    int node = (blockIdx.x * blockDim.x + threadIdx.x) >> 5;
    int lane = threadIdx.x & 31;
    if (node >= n) return;
    int beg = d_rowptr[node], end = d_rowptr[node + 1];
    float adi = d_ad[node];
    float dvi = d_dinv[node];

    float4 gat, gcn;
    float4 sg = make_float4(0, 0, 0, 0);
    float den;

    {
        float w = __expf(lrelu02(d_as[node] + adi));
        den = w;
        float nn = dvi * dvi;
        float4 xv = ((const float4*)(x + (size_t)node * FIN))[lane];
        gat = make_float4(w * xv.x, w * xv.y, w * xv.z, w * xv.w);
        gcn = make_float4(nn * xv.x, nn * xv.y, nn * xv.z, nn * xv.w);
    }

    for (int j0 = beg; j0 < end; j0 += 32) {
        int myj = j0 + lane;
        int s = 0; float w = 0.f, nrm = 0.f;
        if (myj < end) {
            s = d_srclist[myj];
            w = __expf(lrelu02(d_as[s] + adi));
            nrm = d_dinv[s] * dvi;
        }
        int cnt = min(32, end - j0);
        for (int q = 0; q < cnt; q++) {
            int   ss = __shfl_sync(0xffffffffu, s, q);
            float wq = __shfl_sync(0xffffffffu, w, q);
            float nq = __shfl_sync(0xffffffffu, nrm, q);
            float4 xv = ((const float4*)(x + (size_t)ss * FIN))[lane];
            gat.x += wq * xv.x; gat.y += wq * xv.y; gat.z += wq * xv.z; gat.w += wq * xv.w;
            gcn.x += nq * xv.x; gcn.y += nq * xv.y; gcn.z += nq * xv.z; gcn.w += nq * xv.w;
            sg.x += xv.x; sg.y += xv.y; sg.z += xv.z; sg.w += xv.w;
            den += wq;
        }
    }

    float invden = 1.0f / den;
    float invcnt = 1.0f / fmaxf((float)(end - beg), 1.0f);
    float4 og = make_float4(gat.x * invden, gat.y * invden,
                            gat.z * invden, gat.w * invden);
    float4 om = make_float4(sg.x * invcnt, sg.y * invcnt,
                            sg.z * invcnt, sg.w * invcnt);
    ((float4*)(d_scr + (size_t)node * 128))[lane] = og;
    ((float4*)(d_scr + (size_t)MAXN * 128 + (size_t)node * 128))[lane] = gcn;
    ((float4*)(d_meanb + (size_t)node * HH))[lane] = om;
}

__global__ void bn_final_kernel(const float* __restrict__ gamma,
                                const float* __restrict__ beta, int n) {
    int c = threadIdx.x;
    if (c < C3) {
        float invn = 1.0f / (float)n;
        float mu = d_sum[c] * invn;
        float var = d_sumsq[c] * invn - mu * mu;
        float r = rsqrtf(var + 1e-5f);
        d_bns[c] = r * gamma[c];
        d_bnt[c] = beta[c] - mu * r * gamma[c];
    }
}

// ---------------- TF32 tensor-core GEMM (proven mainloop + STS.128 tile stores) ----------------
__device__ __forceinline__ uint32_t f2tf32(float f) {
    uint32_t o; asm("cvt.rna.tf32.f32 %0, %1;" : "=r"(o) : "f"(f)); return o;
}
__device__ __forceinline__ float tfr(float f) { return __uint_as_float(f2tf32(f)); }
__device__ __forceinline__ void mma_tf32(float* c, const uint32_t* a, const uint32_t* b) {
    asm volatile(
        "mma.sync.aligned.m16n8k8.row.col.f32.tf32.tf32.f32 "
        "{%0,%1,%2,%3}, {%4,%5,%6,%7}, {%8,%9}, {%0,%1,%2,%3};"
        : "+f"(c[0]), "+f"(c[1]), "+f"(c[2]), "+f"(c[3])
        : "r"(a[0]), "r"(a[1]), "r"(a[2]), "r"(a[3]), "r"(b[0]), "r"(b[1]));
}

// statsOff >= 0: accumulate column sums/sumsq of written values into d_sum/d_sumsq.
__global__ void __launch_bounds__(256)
gemm_tc_kernel(int aTag, const float* aExt, int lda,
               int bTag, const float* bExt, int ldb,
               int cTag, float* cExt, int ldc,
               int M, int K, int Ncol,
               const float* __restrict__ bias,
               int addTag, int ldadd,
               int scaleTag, int shiftTag, int reluA, int statsOff) {
    const float* __restrict__ A = resolve_c(aTag, aExt);
    const float* __restrict__ B = resolve_c(bTag, bExt);
    float* __restrict__ C = resolve_m(cTag, cExt);
    const float* __restrict__ addv   = (addTag   == TAG_EXT) ? nullptr : resolve_c(addTag, nullptr);
    const float* __restrict__ ascale = (scaleTag == TAG_EXT) ? nullptr : resolve_c(scaleTag, nullptr);
    const float* __restrict__ ashift = (shiftTag == TAG_EXT) ? nullptr : resolve_c(shiftTag, nullptr);

    __shared__ float As[BM][ASP];
    __shared__ float Bs[BKT][BSP];

    int tid  = threadIdx.x;
    int warp = tid >> 5, lane = tid & 31;
    int wm = warp & 3, wn = warp >> 2;
    int gid = lane >> 2, tig = lane & 3;
    int row0 = blockIdx.y * BM, col0 = blockIdx.x * BN;

    float acc[2][8][4];
    #pragma unroll
    for (int mt = 0; mt < 2; mt++)
        #pragma unroll
        for (int nt = 0; nt < 8; nt++)
            #pragma unroll
            for (int r = 0; r < 4; r++) acc[mt][nt][r] = 0.f;

    int a_m  = tid >> 3;
    int a_k4 = (tid & 7) * 4;

    for (int k0 = 0; k0 < K; k0 += BKT) {
        #pragma unroll
        for (int i = 0; i < 4; i++) {
            int m = a_m + 32 * i;
            int gm = row0 + m;
            float4 v = make_float4(0.f, 0.f, 0.f, 0.f);
            if (gm < M) v = *(const float4*)(A + (size_t)gm * lda + k0 + a_k4);
            if (ascale) {
                int gk = k0 + a_k4;
                v.x = v.x * ascale[gk + 0] + ashift[gk + 0];
                v.y = v.y * ascale[gk + 1] + ashift[gk + 1];
                v.z = v.z * ascale[gk + 2] + ashift[gk + 2];
                v.w = v.w * ascale[gk + 3] + ashift[gk + 3];
            }
            if (reluA) {
                v.x = fmaxf(v.x, 0.f); v.y = fmaxf(v.y, 0.f);
                v.z = fmaxf(v.z, 0.f); v.w = fmaxf(v.w, 0.f);
            }
            float4 o = make_float4(tfr(v.x), tfr(v.y), tfr(v.z), tfr(v.w));
            *(float4*)&As[m][a_k4] = o;
        }
        #pragma unroll
        for (int i = 0; i < 4; i++) {
            int idx = tid + 256 * i;
            int k = idx >> 5;
            int nc = (idx & 31) * 4;
            float4 v = make_float4(0.f, 0.f, 0.f, 0.f);
            if (col0 + nc < Ncol)
                v = *(const float4*)(B + (size_t)(k0 + k) * ldb + col0 + nc);
            float4 o = make_float4(tfr(v.x), tfr(v.y), tfr(v.z), tfr(v.w));
            *(float4*)&Bs[k][nc] = o;
        }
        __syncthreads();

        #pragma unroll
        for (int ks = 0; ks < BKT; ks += 8) {
            uint32_t af[2][4];
            #pragma unroll
            for (int mt = 0; mt < 2; mt++) {
                int m = wm * 32 + mt * 16;
                af[mt][0] = __float_as_uint(As[m + gid    ][ks + tig    ]);
                af[mt][1] = __float_as_uint(As[m + gid + 8][ks + tig    ]);
                af[mt][2] = __float_as_uint(As[m + gid    ][ks + tig + 4]);
                af[mt][3] = __float_as_uint(As[m + gid + 8][ks + tig + 4]);
            }
            uint32_t bf[8][2];
            #pragma unroll
            for (int nt = 0; nt < 8; nt++) {
                int nn = wn * 64 + nt * 8 + gid;
                bf[nt][0] = __float_as_uint(Bs[ks + tig    ][nn]);
                bf[nt][1] = __float_as_uint(Bs[ks + tig + 4][nn]);
            }
            #pragma unroll
            for (int mt = 0; mt < 2; mt++)
                #pragma unroll
                for (int nt = 0; nt < 8; nt++)
                    mma_tf32(acc[mt][nt], af[mt], bf[nt]);
        }
        __syncthreads();
    }

    #pragma unroll
    for (int nt = 0; nt < 8; nt++) {
        int n0 = col0 + wn * 64 + nt * 8 + 2 * tig;
        float sum0 = 0.f, sum1 = 0.f, sq0 = 0.f, sq1 = 0.f;
        if (n0 < Ncol) {
            float b0 = bias ? bias[n0] : 0.f;
            float b1 = bias ? bias[n0 + 1] : 0.f;
            #pragma unroll
            for (int mt = 0; mt < 2; mt++) {
                #pragma unroll
                for (int half = 0; half < 2; half++) {
                    int r = row0 + wm * 32 + mt * 16 + gid + half * 8;
                    if (r < M) {
                        float v0 = acc[mt][nt][half * 2 + 0] + b0;
                        float v1 = acc[mt][nt][half * 2 + 1] + b1;
                        if (addv) {
                            v0 += addv[(size_t)r * ldadd + n0];
                            v1 += addv[(size_t)r * ldadd + n0 + 1];
                        }
                        *(float2*)(C + (size_t)r * ldc + n0) = make_float2(v0, v1);
                        sum0 += v0; sq0 += v0 * v0;
                        sum1 += v1; sq1 += v1 * v1;
                    }
                }
            }
        }
        if (statsOff >= 0) {
            #pragma unroll
            for (int off = 16; off >= 4; off >>= 1) {
                sum0 += __shfl_down_sync(0xffffffffu, sum0, off);
                sq0  += __shfl_down_sync(0xffffffffu, sq0,  off);
                sum1 += __shfl_down_sync(0xffffffffu, sum1, off);
                sq1  += __shfl_down_sync(0xffffffffu, sq1,  off);
            }
            if (gid == 0 && n0 < Ncol) {
                int c = statsOff + n0 - col0;
                atomicAdd(&d_sum[c],     sum0);
                atomicAdd(&d_sumsq[c],   sq0);
                atomicAdd(&d_sum[c + 1], sum1);
                atomicAdd(&d_sumsq[c + 1], sq1);
            }
        }
    }
}

// grouped convs: p0 aggG@Wg+bg -> h[:,0:128] (+stats); p1 aggC@Wc+bc -> h[:,128:256] (+stats);
// p2 x@Wr -> xr (no stats)
__global__ void __launch_bounds__(256)
conv3_kernel(int rbn, int M, const float* __restrict__ x,
             const float* __restrict__ Wg, const float* __restrict__ Wc,
             const float* __restrict__ Wr,
             const float* __restrict__ b_gat, const float* __restrict__ b_gcn) {
    int p = blockIdx.x / rbn;
    int rb = blockIdx.x % rbn;
    const float *A, *B, *bias; float* C; int ldc, statsOff;
    if (p == 0)      { A = d_scr;                      B = Wg; C = d_h;       bias = b_gat; ldc = C3;  statsOff = 0; }
    else if (p == 1) { A = d_scr + (size_t)MAXN * 128; B = Wc; C = d_h + 128; bias = b_gcn; ldc = C3;  statsOff = 128; }
    else             { A = x;                          B = Wr; C = d_scr + (size_t)2 * MAXN * 128; bias = nullptr; ldc = 128; statsOff = -1; }
    const int K = 128, lda = 128, ldb = 128;

    __shared__ float As[BM][ASP];
    __shared__ float Bs[BKT][BSP];

    int tid  = threadIdx.x;
    int warp = tid >> 5, lane = tid & 31;
    int wm = warp & 3, wn = warp >> 2;
    int gid = lane >> 2, tig = lane & 3;
    int row0 = rb * BM;

    float acc[2][8][4];
    #pragma unroll
    for (int mt = 0; mt < 2; mt++)
        #pragma unroll
        for (int nt = 0; nt < 8; nt++)
            #pragma unroll
            for (int r = 0; r < 4; r++) acc[mt][nt][r] = 0.f;

    int a_m  = tid >> 3;
    int a_k4 = (tid & 7) * 4;

    for (int k0 = 0; k0 < K; k0 += BKT) {
        #pragma unroll
        for (int i = 0; i < 4; i++) {
            int m = a_m + 32 * i;
            int gm = row0 + m;
            float4 v = make_float4(0.f, 0.f, 0.f, 0.f);
            if (gm < M) v = *(const float4*)(A + (size_t)gm * lda + k0 + a_k4);
            float4 o = make_float4(tfr(v.x), tfr(v.y), tfr(v.z), tfr(v.w));
            *(float4*)&As[m][a_k4] = o;
        }
        #pragma unroll
        for (int i = 0; i < 4; i++) {
            int idx = tid + 256 * i;
            int k = idx >> 5;
            int nc = (idx & 31) * 4;
            float4 v = *(const float4*)(B + (size_t)(k0 + k) * ldb + nc);
            float4 o = make_float4(tfr(v.x), tfr(v.y), tfr(v.z), tfr(v.w));
            *(float4*)&Bs[k][nc] = o;
        }
        __syncthreads();

        #pragma unroll
        for (int ks = 0; ks < BKT; ks += 8) {
            uint32_t af[2][4];
            #pragma unroll
            for (int mt = 0; mt < 2; mt++) {
                int m = wm * 32 + mt * 16;
                af[mt][0] = __float_as_uint(As[m + gid    ][ks + tig    ]);
                af[mt][1] = __float_as_uint(As[m + gid + 8][ks + tig    ]);
                af[mt][2] = __float_as_uint(As[m + gid    ][ks + tig + 4]);
                af[mt][3] = __float_as_uint(As[m + gid + 8][ks + tig + 4]);
            }
            uint32_t bf[8][2];
            #pragma unroll
            for (int nt = 0; nt < 8; nt++) {
                int nn = wn * 64 + nt * 8 + gid;
                bf[nt][0] = __float_as_uint(Bs[ks + tig    ][nn]);
                bf[nt][1] = __float_as_uint(Bs[ks + tig + 4][nn]);
            }
            #pragma unroll
            for (int mt = 0; mt < 2; mt++)
                #pragma unroll
                for (int nt = 0; nt < 8; nt++)
                    mma_tf32(acc[mt][nt], af[mt], bf[nt]);
        }
        __syncthreads();
    }

    #pragma unroll
    for (int nt = 0; nt < 8; nt++) {
        int n0 = wn * 64 + nt * 8 + 2 * tig;
        float b0 = bias ? bias[n0] : 0.f;
        float b1 = bias ? bias[n0 + 1] : 0.f;
        float sum0 = 0.f, sum1 = 0.f, sq0 = 0.f, sq1 = 0.f;
        #pragma unroll
        for (int mt = 0; mt < 2; mt++) {
            #pragma unroll
            for (int half = 0; half < 2; half++) {
                int r = row0 + wm * 32 + mt * 16 + gid + half * 8;
                if (r < M) {
                    float v0 = acc[mt][nt][half * 2 + 0] + b0;
                    float v1 = acc[mt][nt][half * 2 + 1] + b1;
                    *(float2*)(C + (size_t)r * ldc + n0) = make_float2(v0, v1);
                    sum0 += v0; sq0 += v0 * v0;
                    sum1 += v1; sq1 += v1 * v1;
                }
            }
        }
        if (statsOff >= 0) {
            #pragma unroll
            for (int off = 16; off >= 4; off >>= 1) {
                sum0 += __shfl_down_sync(0xffffffffu, sum0, off);
                sq0  += __shfl_down_sync(0xffffffffu, sq0,  off);
                sum1 += __shfl_down_sync(0xffffffffu, sum1, off);
                sq1  += __shfl_down_sync(0xffffffffu, sq1,  off);
            }
            if (gid == 0) {
                int c = statsOff + n0;
                atomicAdd(&d_sum[c],     sum0);
                atomicAdd(&d_sumsq[c],   sq0);
                atomicAdd(&d_sum[c + 1], sum1);
                atomicAdd(&d_sumsq[c + 1], sq1);
            }
        }
    }
}

static void launch_gemm(int aTag, const float* aExt, int lda,
                        int bTag, const float* bExt, int ldb,
                        int cTag, float* cExt, int ldc,
                        int M, int K, int Ncol,
                        const float* bias,
                        int addTag, int ldadd,
                        int scaleTag, int shiftTag, int reluA, int statsOff) {
    dim3 g((Ncol + BN - 1) / BN, (M + BM - 1) / BM);
    gemm_tc_kernel<<<g, 256>>>(aTag, aExt, lda, bTag, bExt, ldb, cTag, cExt, ldc,
                               M, K, Ncol, bias, addTag, ldadd,
                               scaleTag, shiftTag, reluA, statsOff);
}

// ---------------- launch ----------------
extern "C" void kernel_launch(void* const* d_in, const int* in_sizes, int n_in,
                              void* d_out, int out_size) {
    const float* x        = (const float*)d_in[0];
    const void*  ei       = d_in[1];
    const float* W_gat    = (const float*)d_in[2];
    const float* att_src  = (const float*)d_in[3];
    const float* att_dst  = (const float*)d_in[4];
    const float* b_gat    = (const float*)d_in[5];
    const float* W_gcn    = (const float*)d_in[6];
    const float* b_gcn    = (const float*)d_in[7];
    const float* W_sage_l = (const float*)d_in[8];
    const float* b_sage_l = (const float*)d_in[9];
    const float* W_sage_r = (const float*)d_in[10];
    const float* W1       = (const float*)d_in[11];
    const float* b1       = (const float*)d_in[12];
    const float* W2       = (const float*)d_in[13];
    const float* b2       = (const float*)d_in[14];
    const float* W3       = (const float*)d_in[15];
    const float* b3       = (const float*)d_in[16];
    const float* gamma    = (const float*)d_in[17];
    const float* beta     = (const float*)d_in[18];
    float* out = (float*)d_out;

    int N = in_sizes[0] / FIN;
    int E = in_sizes[1] / 2;
    int rbn = (N + BM - 1) / BM;
    int sbn = (N + 255) / 256;

    prep_kernel<<<(N + 255) / 256, 256>>>(ei, E, N, W_gat, att_src, att_dst);
    asad_kernel<<<(N * 32 + 255) / 256, 256>>>(x, N);
    count_deg_kernel<<<(E + 255) / 256, 256>>>(ei, E, N);
    scan1_kernel<<<sbn, 256>>>(N);
    scan2_kernel<<<1, 256>>>(sbn, N);
    scan3_kernel<<<sbn, 256>>>(N);
    scatter_kernel<<<(E + 255) / 256, 256>>>(ei, E, N);
    gather_kernel<<<(N * 32 + 255) / 256, 256>>>(x, N);
    // grouped convs (+BN stats for h[:,0:256])
    conv3_kernel<<<3 * rbn, 256>>>(rbn, N, x, W_gat, W_gcn, W_sage_r, b_gat, b_gcn);
    // sage: h[:,256:384] = meanb @ W_sage_l + b_sage_l + xr (+BN stats for cols 256:384)
    launch_gemm(TAG_MEANB, nullptr, HH, TAG_EXT, W_sage_l, HH, TAG_H256, nullptr, C3,
                N, HH, HH, b_sage_l, TAG_XR, 128, TAG_EXT, TAG_EXT, 0, 256);
    bn_final_kernel<<<1, C3>>>(gamma, beta, N);
    // MLP1
    launch_gemm(TAG_H, nullptr, C3, TAG_EXT, W1, 256, TAG_Z1, nullptr, 256,
                N, C3, 256, b1, TAG_EXT, 0, TAG_BNS, TAG_BNT, 1, -1);
    // MLP2
    launch_gemm(TAG_Z1, nullptr, 256, TAG_EXT, W2, 128, TAG_Z2, nullptr, 128,
                N, 256, 128, b2, TAG_EXT, 0, TAG_EXT, TAG_EXT, 1, -1);
    // MLP3
    launch_gemm(TAG_Z2, nullptr, 128, TAG_EXT, W3, 40, TAG_EXT, out, 40,
                N, 128, 40, b3, TAG_EXT, 0, TAG_EXT, TAG_EXT, 1, -1);
}